// round 16
// baseline (speedup 1.0000x reference)
#include <cuda_runtime.h>
#include <math.h>
#include <stdint.h>

#define BATCH 128

// ----------------- scratch buffers -----------------
__device__ float d_c1[BATCH*96*55*55];
__device__ float d_l1[BATCH*96*27*27];
__device__ float d_c2[BATCH*256*27*27];
__device__ float d_l2[BATCH*256*13*13];
__device__ float d_c3[BATCH*384*13*13];
__device__ float d_c4[BATCH*384*13*13];
__device__ float d_c5[BATCH*256*13*13];
__device__ float d_feat[BATCH*9216];
__device__ float d_h1[BATCH*4096];
__device__ float d_h2[BATCH*4096];
__device__ float d_out0[BATCH*100];
__device__ float d_g2[BATCH*4096];
__device__ float d_mask[BATCH*36];
__device__ float d_h1b[BATCH*4096];
__device__ float d_h2b[BATCH*4096];
__device__ float d_outb[BATCH*100];
__device__ float d_clsb[BATCH];
__device__ float d_w6r[4096*36];
__device__ float d_part[8*BATCH*4096];

// ----------------- f32x2 helpers -----------------
__device__ __forceinline__ unsigned long long pack2(float a, float b) {
    unsigned long long r;
    asm("mov.b64 %0, {%1, %2};" : "=l"(r) : "r"(__float_as_uint(a)), "r"(__float_as_uint(b)));
    return r;
}
__device__ __forceinline__ void fma2(unsigned long long& d, unsigned long long a, unsigned long long b) {
    asm("fma.rn.f32x2 %0, %1, %2, %0;" : "+l"(d) : "l"(a), "l"(b));
}
__device__ __forceinline__ float2 unpack2(unsigned long long v) {
    unsigned lo, hi;
    asm("mov.b64 {%0, %1}, %2;" : "=r"(lo), "=r"(hi) : "l"(v));
    float2 f; f.x = __uint_as_float(lo); f.y = __uint_as_float(hi); return f;
}

// ----------------- implicit-GEMM conv, f32x2, double-buffered (frozen) -----------------
template<int CING, int HH, int WW, int COUTG, int COUTT, int KH, int KW,
         int STR, int PAD, int OH, int OW, int GROUPS, int MT>
__global__ __launch_bounds__(256, 2)
void conv_f2(const float* __restrict__ x, const float* __restrict__ w,
             const float* __restrict__ bias, float* __restrict__ out, float scale)
{
    constexpr int K    = CING*KH*KW;
    constexpr int CINT = CING*GROUPS;
    constexpr int OHW  = OH*OW;
    constexpr int MI   = MT/16;
    constexpr int AS   = MT + 4;
    constexpr int NCH  = (K + 15)/16;

    const int g    = blockIdx.z;
    const int pix0 = blockIdx.x * 128;
    const int m0   = blockIdx.y * MT;

    __shared__ __align__(16) float As[2][16][AS];
    __shared__ __align__(16) float Bs[2][16][132];

    const int t  = threadIdx.x;
    const int tx = t & 15, ty = t >> 4;
    const int lk = t & 15, lr = t >> 4;

    int ihb[8], iwb[8], xb[8];
    #pragma unroll
    for (int p = 0; p < 8; ++p) {
        int pix = pix0 + lr + p*16;
        int n   = pix / OHW; int rem = pix - n*OHW;
        int oh  = rem / OW;  int ow  = rem - oh*OW;
        ihb[p] = oh*STR - PAD; iwb[p] = ow*STR - PAD;
        xb[p]  = (n*CINT + g*CING)*HH*WW;
    }

    const float* wbase = w + (size_t)(g*COUTG + m0)*K;

    float ra[MI], rb[8];

    auto loadA = [&](int k0) {
        int kg = k0 + lk; bool kv = kg < K;
        #pragma unroll
        for (int p = 0; p < MI; ++p)
            ra[p] = kv ? wbase[(lr + p*16)*K + kg] : 0.f;
    };
    auto loadB = [&](int k0) {
        int kg = k0 + lk; bool kv = kg < K;
        int kc = kv ? kg : 0;
        int ic = kc / (KH*KW);
        int r2 = kc - ic*(KH*KW);
        int kh = r2 / KW, kw = r2 - kh*KW;
        #pragma unroll
        for (int p = 0; p < 8; ++p) {
            int ih = ihb[p] + kh, iw = iwb[p] + kw;
            float v = 0.f;
            if (kv && (unsigned)ih < (unsigned)HH && (unsigned)iw < (unsigned)WW)
                v = x[xb[p] + ic*HH*WW + ih*WW + iw] * scale;
            rb[p] = v;
        }
    };
    auto stTile = [&](int buf) {
        #pragma unroll
        for (int p = 0; p < MI; ++p) As[buf][lk][lr + p*16] = ra[p];
        #pragma unroll
        for (int p = 0; p < 8;  ++p) Bs[buf][lk][lr + p*16] = rb[p];
    };

    unsigned long long acc[MI][4];
    #pragma unroll
    for (int i = 0; i < MI; ++i)
        #pragma unroll
        for (int j = 0; j < 4; ++j) acc[i][j] = 0ull;

    loadA(0); loadB(0); stTile(0);
    __syncthreads();

    for (int c = 0; c < NCH; ++c) {
        int buf = c & 1;
        if (c + 1 < NCH) { loadA((c+1)*16); loadB((c+1)*16); }
        #pragma unroll
        for (int kk = 0; kk < 16; ++kk) {
            unsigned long long b2[4];
            #pragma unroll
            for (int j = 0; j < 4; ++j)
                b2[j] = *(const unsigned long long*)&Bs[buf][kk][tx*2 + j*32];
            #pragma unroll
            for (int i = 0; i < MI; ++i) {
                float av = As[buf][kk][ty + i*16];
                unsigned long long a2 = pack2(av, av);
                #pragma unroll
                for (int j = 0; j < 4; ++j) fma2(acc[i][j], a2, b2[j]);
            }
        }
        if (c + 1 < NCH) stTile(buf ^ 1);
        __syncthreads();
    }

    #pragma unroll
    for (int i = 0; i < MI; ++i) {
        int m = m0 + ty + i*16;
        float bv = bias[g*COUTG + m];
        #pragma unroll
        for (int j = 0; j < 4; ++j) {
            float2 v = unpack2(acc[i][j]);
            int pix = pix0 + tx*2 + j*32;
            int n0_ = pix / OHW;       int r0_ = pix - n0_*OHW;
            int n1_ = (pix+1) / OHW;   int r1_ = (pix+1) - n1_*OHW;
            out[((size_t)(n0_*COUTT + g*COUTG + m))*OHW + r0_] = fmaxf(v.x + bv, 0.f);
            out[((size_t)(n1_*COUTT + g*COUTG + m))*OHW + r1_] = fmaxf(v.y + bv, 0.f);
        }
    }
}

// ----------------- split-K GEMM, f32x2, 64x64 tiles (frozen) -----------------
template<int TRANSB>
__global__ __launch_bounds__(256, 2)
void gemm_f2(const float* __restrict__ A, const float* __restrict__ B,
             float* __restrict__ part, int M, int N, int K, int Kc)
{
    __shared__ __align__(16) float As[2][16][68];
    __shared__ __align__(16) float Bs[2][16][68];
    const int m0 = blockIdx.y*64, n0 = blockIdx.x*64;
    const int z  = blockIdx.z;
    const int kb = z*Kc;
    const int ke = min(K, kb + Kc);
    const int t = threadIdx.x, tx = t & 15, ty = t >> 4;
    const int lk = t & 15, lr = t >> 4;
    const int lr2 = t & 63, lk2 = t >> 6;

    float ra[4], rbv[4];
    auto loadA = [&](int k0) {
        int kg = k0 + lk; bool kv = kg < ke;
        #pragma unroll
        for (int p = 0; p < 4; ++p)
            ra[p] = kv ? A[(size_t)(m0 + lr + p*16)*K + kg] : 0.f;
    };
    auto loadB = [&](int k0) {
        if (TRANSB) {
            int kg = k0 + lk; bool kv = kg < ke;
            #pragma unroll
            for (int p = 0; p < 4; ++p)
                rbv[p] = kv ? B[(size_t)(n0 + lr + p*16)*K + kg] : 0.f;
        } else {
            #pragma unroll
            for (int p = 0; p < 4; ++p) {
                int kg = k0 + lk2 + p*4;
                rbv[p] = (kg < ke) ? B[(size_t)kg*N + n0 + lr2] : 0.f;
            }
        }
    };
    auto stT = [&](int buf) {
        #pragma unroll
        for (int p = 0; p < 4; ++p) As[buf][lk][lr + p*16] = ra[p];
        if (TRANSB) {
            #pragma unroll
            for (int p = 0; p < 4; ++p) Bs[buf][lk][lr + p*16] = rbv[p];
        } else {
            #pragma unroll
            for (int p = 0; p < 4; ++p) Bs[buf][lk2 + p*4][lr2] = rbv[p];
        }
    };

    unsigned long long acc[4][2];
    #pragma unroll
    for (int i = 0; i < 4; ++i) { acc[i][0] = 0ull; acc[i][1] = 0ull; }

    const int nch = (ke - kb + 15)/16;
    loadA(kb); loadB(kb); stT(0);
    __syncthreads();

    for (int c = 0; c < nch; ++c) {
        int buf = c & 1;
        if (c + 1 < nch) { loadA(kb + (c+1)*16); loadB(kb + (c+1)*16); }
        #pragma unroll
        for (int kk = 0; kk < 16; ++kk) {
            unsigned long long b2[2];
            #pragma unroll
            for (int j = 0; j < 2; ++j)
                b2[j] = *(const unsigned long long*)&Bs[buf][kk][tx*2 + j*32];
            #pragma unroll
            for (int i = 0; i < 4; ++i) {
                float av = As[buf][kk][ty + i*16];
                unsigned long long a2 = pack2(av, av);
                #pragma unroll
                for (int j = 0; j < 2; ++j) fma2(acc[i][j], a2, b2[j]);
            }
        }
        if (c + 1 < nch) stT(buf ^ 1);
        __syncthreads();
    }

    #pragma unroll
    for (int i = 0; i < 4; ++i) {
        int m = m0 + ty + i*16;
        #pragma unroll
        for (int j = 0; j < 2; ++j) {
            float2 v = unpack2(acc[i][j]);
            int n = n0 + tx*2 + j*32;
            *(float2*)&part[((size_t)z*M + m)*N + n] = v;
        }
    }
}

// ----------------- masked-A variant (head#2 first GEMM) -----------------
__global__ __launch_bounds__(256, 2)
void gemm_f2m(const float* __restrict__ A, const float* __restrict__ B,
              const float* __restrict__ mask,
              float* __restrict__ part, int M, int N, int K, int Kc)
{
    __shared__ __align__(16) float As[2][16][68];
    __shared__ __align__(16) float Bs[2][16][68];
    const int m0 = blockIdx.y*64, n0 = blockIdx.x*64;
    const int z  = blockIdx.z;
    const int kb = z*Kc;
    const int ke = min(K, kb + Kc);
    const int t = threadIdx.x, tx = t & 15, ty = t >> 4;
    const int lk = t & 15, lr = t >> 4;

    float ra[4], rbv[4];
    auto loadA = [&](int k0) {
        int kg = k0 + lk; bool kv = kg < ke;
        int s = kg % 36;
        #pragma unroll
        for (int p = 0; p < 4; ++p) {
            int row = m0 + lr + p*16;
            float mv = mask[row*36 + s];
            ra[p] = kv ? A[(size_t)row*K + kg] * mv : 0.f;
        }
    };
    auto loadB = [&](int k0) {
        int kg = k0 + lk; bool kv = kg < ke;
        #pragma unroll
        for (int p = 0; p < 4; ++p)
            rbv[p] = kv ? B[(size_t)(n0 + lr + p*16)*K + kg] : 0.f;
    };
    auto stT = [&](int buf) {
        #pragma unroll
        for (int p = 0; p < 4; ++p) As[buf][lk][lr + p*16] = ra[p];
        #pragma unroll
        for (int p = 0; p < 4; ++p) Bs[buf][lk][lr + p*16] = rbv[p];
    };

    unsigned long long acc[4][2];
    #pragma unroll
    for (int i = 0; i < 4; ++i) { acc[i][0] = 0ull; acc[i][1] = 0ull; }

    const int nch = (ke - kb + 15)/16;
    loadA(kb); loadB(kb); stT(0);
    __syncthreads();

    for (int c = 0; c < nch; ++c) {
        int buf = c & 1;
        if (c + 1 < nch) { loadA(kb + (c+1)*16); loadB(kb + (c+1)*16); }
        #pragma unroll
        for (int kk = 0; kk < 16; ++kk) {
            unsigned long long b2[2];
            #pragma unroll
            for (int j = 0; j < 2; ++j)
                b2[j] = *(const unsigned long long*)&Bs[buf][kk][tx*2 + j*32];
            #pragma unroll
            for (int i = 0; i < 4; ++i) {
                float av = As[buf][kk][ty + i*16];
                unsigned long long a2 = pack2(av, av);
                #pragma unroll
                for (int j = 0; j < 2; ++j) fma2(acc[i][j], a2, b2[j]);
            }
        }
        if (c + 1 < nch) stT(buf ^ 1);
        __syncthreads();
    }

    #pragma unroll
    for (int i = 0; i < 4; ++i) {
        int m = m0 + ty + i*16;
        #pragma unroll
        for (int j = 0; j < 2; ++j) {
            float2 v = unpack2(acc[i][j]);
            int n = n0 + tx*2 + j*32;
            *(float2*)&part[((size_t)z*M + m)*N + n] = v;
        }
    }
}

// ----------------- split-K reduce + bias/relu epilogue (N=4096) -----------------
__global__ void reduce_k(const float* __restrict__ part, const float* __restrict__ bias,
                         const float* __restrict__ maskref, float* __restrict__ C,
                         int MN, int S, int doRelu)
{
    int i = blockIdx.x*256 + threadIdx.x;
    if (i >= MN) return;
    float s = 0.f;
    for (int z = 0; z < S; ++z) s += part[(size_t)z*MN + i];
    if (bias) s += bias[i & 4095];
    if (doRelu) s = fmaxf(s, 0.f);
    if (maskref) s = (maskref[i] > 0.f) ? s : 0.f;
    C[i] = s;
}

// ----------------- split-K reduce producing h2 AND g2 -----------------
__global__ void reduce_g2_k(const float* __restrict__ part, const float* __restrict__ bias,
                            const float* __restrict__ wc, const int* __restrict__ gt,
                            float* __restrict__ h2, float* __restrict__ g2, int S)
{
    int i = blockIdx.x*256 + threadIdx.x;
    if (i >= BATCH*4096) return;
    int n = i >> 12, j = i & 4095;
    float s = 0.f;
    for (int z = 0; z < S; ++z) s += part[(size_t)z*BATCH*4096 + i];
    s += bias[j];
    s = fmaxf(s, 0.f);
    h2[i] = s;
    g2[i] = (s > 0.f) ? wc[(size_t)gt[n]*4096 + j] : 0.f;
}

// ----------------- fused gradient tail: reduce(g1) + spatial-mean GEMM + RSC mask -----------------
__global__ void gradtail_k(const float* __restrict__ part, const float* __restrict__ h1,
                           const float* __restrict__ w6r, const float* __restrict__ u,
                           const int* __restrict__ flag, float* __restrict__ mask)
{
    __shared__ float gs[4096];
    __shared__ float smrow[36];
    const int n = blockIdx.x, t = threadIdx.x;
    const int warp = t >> 5, lane = t & 31;

    for (int j = t; j < 4096; j += 256) {
        size_t i = (size_t)n*4096 + j;
        float s = 0.f;
        #pragma unroll
        for (int z = 0; z < 8; ++z) s += part[(size_t)z*BATCH*4096 + i];
        gs[j] = (h1[i] > 0.f) ? s : 0.f;
    }
    __syncthreads();

    for (int s = warp; s < 36; s += 8) {
        float acc = 0.f;
        for (int k = lane; k < 4096; k += 32) acc += gs[k] * w6r[k*36 + s];
        #pragma unroll
        for (int o = 16; o; o >>= 1) acc += __shfl_xor_sync(0xffffffffu, acc, o);
        if (lane == 0) smrow[s] = acc;
    }
    __syncthreads();

    if (t == 0) {
        if (*flag == 0) {
            for (int s = 0; s < 36; ++s) mask[n*36 + s] = 1.f;
            return;
        }
        float v[36], tmp[36], sc[36], mk[36];
        for (int s = 0; s < 36; ++s) { v[s] = smrow[s]; tmp[s] = v[s]; mk[s] = 1.f; }
        float th = 0.f;
        for (int it = 0; it < 13; ++it) {
            int bi = 0; float bv = tmp[0];
            for (int s = 1; s < 36; ++s) if (tmp[s] > bv) { bv = tmp[s]; bi = s; }
            th = bv; tmp[bi] = -3.4e38f;
        }
        for (int s = 0; s < 36; ++s) sc[s] = (v[s] >= th) ? u[n*36 + s] : -1.f;
        for (int it = 0; it < 12; ++it) {
            int bi = 0; float bv = sc[0];
            for (int s = 1; s < 36; ++s) if (sc[s] > bv) { bv = sc[s]; bi = s; }
            mk[bi] = 0.f; sc[bi] = -2.f;
        }
        for (int s = 0; s < 36; ++s) mask[n*36 + s] = mk[s];
    }
}

// ----------------- fused maxpool(3,2) + LRN(n=5) -----------------
template<int C, int HI, int HO>
__global__ void poollrn_kernel(const float* __restrict__ in, float* __restrict__ out)
{
    __shared__ float pl[C*HO];
    int b = blockIdx.x;
    int n = b / HO, oy = b % HO;
    for (int idx = threadIdx.x; idx < C*HO; idx += 256) {
        int c = idx / HO, ox = idx - c*HO;
        const float* p = in + ((size_t)(n*C + c)*HI + oy*2)*HI + ox*2;
        float m = -3.4e38f;
        #pragma unroll
        for (int a = 0; a < 3; ++a)
            #pragma unroll
            for (int bq = 0; bq < 3; ++bq)
                m = fmaxf(m, p[a*HI + bq]);
        pl[idx] = m;
    }
    __syncthreads();
    for (int idx = threadIdx.x; idx < C*HO; idx += 256) {
        int c = idx / HO, ox = idx - c*HO;
        float sum = 0.f;
        #pragma unroll
        for (int d = -2; d <= 2; ++d) {
            int cc = c + d;
            if (cc >= 0 && cc < C) {
                float v = pl[cc*HO + ox];
                sum = fmaf(v, v, sum);
            }
        }
        float r = rsqrtf(fmaf(2e-5f, sum, 1.0f));
        out[((size_t)(n*C + c)*HO + oy)*HO + ox] = pl[idx] * r * sqrtf(r);
    }
}

// ----------------- maxpool 3x3 stride 2 (final 13->6) -----------------
template<int C, int HI, int HO>
__global__ void pool_kernel(const float* __restrict__ in, float* __restrict__ out)
{
    constexpr int TOT = BATCH*C*HO*HO;
    int idx = blockIdx.x*256 + threadIdx.x;
    if (idx >= TOT) return;
    int ox = idx % HO;
    int tq = idx / HO;
    int oy = tq % HO;
    int nc = tq / HO;
    const float* p = in + ((size_t)nc*HI + oy*2)*HI + ox*2;
    float m = -3.4e38f;
    #pragma unroll
    for (int a = 0; a < 3; ++a)
        #pragma unroll
        for (int b = 0; b < 3; ++b)
            m = fmaxf(m, p[a*HI + b]);
    out[idx] = m;
}

// ----------------- fold w6 over channels -----------------
__global__ void w6fold_k(const float* __restrict__ w6, float* __restrict__ w6r)
{
    int i = blockIdx.x*256 + threadIdx.x;
    if (i >= 4096*36) return;
    int j = i / 36, s = i - j*36;
    const float* p = w6 + (size_t)j*9216 + s;
    float acc = 0.f;
    for (int c = 0; c < 256; ++c) acc += p[c*36];
    w6r[i] = acc * (1.f/256.f);
}

// ----------------- classifier dot -----------------
__global__ void cls_kernel(const float* __restrict__ h, const float* __restrict__ wc,
                           const float* __restrict__ bc, float* __restrict__ out)
{
    int n = blockIdx.x;
    int warp = threadIdx.x >> 5, lane = threadIdx.x & 31;
    int c = blockIdx.y*8 + warp;
    if (c >= 100) return;
    const float4* hp = (const float4*)(h + n*4096);
    const float4* wp = (const float4*)(wc + c*4096);
    float s = 0.f;
    for (int k = lane; k < 1024; k += 32) {
        float4 a = hp[k], b = wp[k];
        s += a.x*b.x + a.y*b.y + a.z*b.z + a.w*b.w;
    }
    #pragma unroll
    for (int o = 16; o; o >>= 1) s += __shfl_xor_sync(0xffffffffu, s, o);
    if (lane == 0) out[n*100 + c] = s + bc[c];
}

// ----------------- softmax probability at gt (head#1, side stream) -----------------
__global__ void softgt_kernel(const float* __restrict__ logits, const int* __restrict__ gt,
                              float* __restrict__ cls)
{
    int n = blockIdx.x;
    int lane = threadIdx.x;
    float m = -3.4e38f;
    for (int c = lane; c < 100; c += 32) m = fmaxf(m, logits[n*100 + c]);
    #pragma unroll
    for (int o = 16; o; o >>= 1) m = fmaxf(m, __shfl_xor_sync(0xffffffffu, m, o));
    float s = 0.f;
    for (int c = lane; c < 100; c += 32) s += expf(logits[n*100 + c] - m);
    #pragma unroll
    for (int o = 16; o; o >>= 1) s += __shfl_xor_sync(0xffffffffu, s, o);
    if (lane == 0) cls[n] = expf(logits[n*100 + gt[n]] - m) / s;
}

// ----------------- fused head#2 softmax@gt + keep decision + final row select -----------------
// 1 block x 1024 threads; warp w handles rows {w, w+32, ...} with softgt's exact
// lane-stride + shfl-tree arithmetic (bit-identical clsa), then verbatim keepsel.
__global__ void finsel_k(const float* __restrict__ outb, const int* __restrict__ gt,
                         const float* __restrict__ clsb, const float* __restrict__ out0,
                         float* __restrict__ out)
{
    __shared__ float cv[BATCH];
    __shared__ float thf;
    const int t = threadIdx.x, warp = t >> 5, lane = t & 31;

    for (int n = warp; n < BATCH; n += 32) {
        float m = -3.4e38f;
        for (int c = lane; c < 100; c += 32) m = fmaxf(m, outb[n*100 + c]);
        #pragma unroll
        for (int o = 16; o; o >>= 1) m = fmaxf(m, __shfl_xor_sync(0xffffffffu, m, o));
        float s = 0.f;
        for (int c = lane; c < 100; c += 32) s += expf(outb[n*100 + c] - m);
        #pragma unroll
        for (int o = 16; o; o >>= 1) s += __shfl_xor_sync(0xffffffffu, s, o);
        if (lane == 0) {
            float clsa = expf(outb[n*100 + gt[n]] - m) / s;
            cv[n] = fmaxf(clsb[n] - clsa - 1e-4f, 0.f);
        }
    }
    __syncthreads();
    if (t == 0) {
        float tmp[BATCH];
        for (int i = 0; i < BATCH; ++i) tmp[i] = cv[i];
        float bv = 0.f;
        for (int it = 0; it < 44; ++it) {
            int bi = 0; bv = tmp[0];
            for (int i = 1; i < BATCH; ++i) if (tmp[i] > bv) { bv = tmp[i]; bi = i; }
            tmp[bi] = -3.4e38f;
        }
        thf = bv;
    }
    __syncthreads();
    for (int i = t; i < BATCH*100; i += 1024) {
        int n = i / 100;
        bool keep = !(cv[n] > thf);
        out[i] = keep ? out0[i] : outb[i];
    }
}

// ----------------- launch -----------------
static float* sym(const void* symbol)
{
    void* p = nullptr;
    cudaGetSymbolAddress(&p, symbol);
    return (float*)p;
}

extern "C" void kernel_launch(void* const* d_in, const int* in_sizes, int n_in,
                              void* d_out, int out_size)
{
    const float* x    = (const float*)d_in[0];
    const int*   gt   = (const int*)  d_in[1];
    const float* u    = (const float*)d_in[2];
    const int*   flag = (const int*)  d_in[3];
    const float* w1 = (const float*)d_in[4];  const float* b1 = (const float*)d_in[5];
    const float* w2 = (const float*)d_in[6];  const float* b2 = (const float*)d_in[7];
    const float* w3 = (const float*)d_in[8];  const float* b3 = (const float*)d_in[9];
    const float* w4 = (const float*)d_in[10]; const float* b4 = (const float*)d_in[11];
    const float* w5 = (const float*)d_in[12]; const float* b5 = (const float*)d_in[13];
    const float* w6 = (const float*)d_in[14]; const float* b6 = (const float*)d_in[15];
    const float* w7 = (const float*)d_in[16]; const float* b7 = (const float*)d_in[17];
    const float* wc = (const float*)d_in[18]; const float* bc = (const float*)d_in[19];
    float* out = (float*)d_out;

    float* c1   = sym(d_c1);   float* l1   = sym(d_l1);
    float* c2   = sym(d_c2);   float* l2   = sym(d_l2);
    float* c3   = sym(d_c3);   float* c4   = sym(d_c4);   float* c5   = sym(d_c5);
    float* feat = sym(d_feat);
    float* h1   = sym(d_h1);   float* h2   = sym(d_h2);   float* out0 = sym(d_out0);
    float* g2   = sym(d_g2);
    float* mask = sym(d_mask);
    float* h1b  = sym(d_h1b);  float* h2b  = sym(d_h2b);
    float* outb = sym(d_outb); float* clsb = sym(d_clsb);
    float* w6r  = sym(d_w6r);  float* part = sym(d_part);

    const int MN = BATCH*4096;

    // side stream + fork/join events (handles cached; identical work every call)
    static cudaStream_t side = nullptr;
    static cudaEvent_t evF1 = nullptr, evJ1 = nullptr, evF2 = nullptr, evJ2 = nullptr;
    if (!side) {
        cudaStreamCreateWithFlags(&side, cudaStreamNonBlocking);
        cudaEventCreateWithFlags(&evF1, cudaEventDisableTiming);
        cudaEventCreateWithFlags(&evJ1, cudaEventDisableTiming);
        cudaEventCreateWithFlags(&evF2, cudaEventDisableTiming);
        cudaEventCreateWithFlags(&evJ2, cudaEventDisableTiming);
        // maximize L1 cache for conv scattered gathers (hint; smem need is 68KB/SM)
        cudaFuncSetAttribute(conv_f2<3,227,227,96,96,11,11,4,0,55,55,1,96>,  cudaFuncAttributePreferredSharedMemoryCarveout, 32);
        cudaFuncSetAttribute(conv_f2<48,27,27,128,256,5,5,1,2,27,27,2,128>,  cudaFuncAttributePreferredSharedMemoryCarveout, 32);
        cudaFuncSetAttribute(conv_f2<256,13,13,384,384,3,3,1,1,13,13,1,128>, cudaFuncAttributePreferredSharedMemoryCarveout, 32);
        cudaFuncSetAttribute(conv_f2<192,13,13,192,384,3,3,1,1,13,13,2,96>,  cudaFuncAttributePreferredSharedMemoryCarveout, 32);
        cudaFuncSetAttribute(conv_f2<192,13,13,128,256,3,3,1,1,13,13,2,128>, cudaFuncAttributePreferredSharedMemoryCarveout, 32);
    }

    // ---- fork: w6fold on side stream, overlapping the conv stack ----
    cudaEventRecord(evF1, 0);
    cudaStreamWaitEvent(side, evF1, 0);
    w6fold_k<<<(4096*36 + 255)/256, 256, 0, side>>>(w6, w6r);
    cudaEventRecord(evJ1, side);

    // ---- feature extractor (frozen) ----
    conv_f2<3,227,227,96,96,11,11,4,0,55,55,1,96><<<dim3(3025,1,1),256>>>(x, w1, b1, c1, 57.6f);
    poollrn_kernel<96,55,27><<<BATCH*27,256>>>(c1, l1);
    conv_f2<48,27,27,128,256,5,5,1,2,27,27,2,128><<<dim3(729,1,2),256>>>(l1, w2, b2, c2, 1.f);
    poollrn_kernel<256,27,13><<<BATCH*13,256>>>(c2, l2);
    conv_f2<256,13,13,384,384,3,3,1,1,13,13,1,128><<<dim3(169,3,1),256>>>(l2, w3, b3, c3, 1.f);
    conv_f2<192,13,13,192,384,3,3,1,1,13,13,2,96><<<dim3(169,2,2),256>>>(c3, w4, b4, c4, 1.f);
    conv_f2<192,13,13,128,256,3,3,1,1,13,13,2,128><<<dim3(169,1,2),256>>>(c4, w5, b5, c5, 1.f);
    pool_kernel<256,13,6><<<4608,256>>>(c5, feat);

    // ---- head #1 (unmasked) : split-K 8 (frozen) ----
    gemm_f2<1><<<dim3(64,2,8),256>>>(feat, w6, part, 128, 4096, 9216, 1152);
    reduce_k<<<2048,256>>>(part, b6, nullptr, h1, MN, 8, 1);
    gemm_f2<1><<<dim3(64,2,8),256>>>(h1, w7, part, 128, 4096, 4096, 512);
    reduce_g2_k<<<2048,256>>>(part, b7, wc, gt, h2, g2, 8);   // produces h2 + g2

    // ---- fork: head#1 cls/softgt on side stream, overlapping the gradient chain ----
    cudaEventRecord(evF2, 0);
    cudaStreamWaitEvent(side, evF2, 0);
    cls_kernel<<<dim3(128,13), 256, 0, side>>>(h2, wc, bc, out0);
    softgt_kernel<<<128, 32, 0, side>>>(out0, gt, clsb);
    cudaEventRecord(evJ2, side);

    // ---- gradient chain: g1-GEMM then fused reduce+smgemm+mask tail ----
    gemm_f2<0><<<dim3(64,2,8),256>>>(g2, w7, part, 128, 4096, 4096, 512);
    cudaStreamWaitEvent(0, evJ1, 0);           // w6r ready
    gradtail_k<<<128,256>>>(part, h1, w6r, u, flag, mask);

    // ---- head #2 (masked) : mask folded into first GEMM's A-load ----
    gemm_f2m<<<dim3(64,2,8),256>>>(feat, w6, mask, part, 128, 4096, 9216, 1152);
    reduce_k<<<2048,256>>>(part, b6, nullptr, h1b, MN, 8, 1);
    gemm_f2<1><<<dim3(64,2,8),256>>>(h1b, w7, part, 128, 4096, 4096, 512);
    reduce_k<<<2048,256>>>(part, b7, nullptr, h2b, MN, 8, 1);
    cls_kernel<<<dim3(128,13),256>>>(h2b, wc, bc, outb);

    // ---- join head#1 cls chain, then fused softmax@gt + keep + select ----
    cudaStreamWaitEvent(0, evJ2, 0);
    finsel_k<<<1,1024>>>(outb, gt, clsb, out0, out);

    (void)in_sizes; (void)n_in; (void)out_size;
}

// round 17
// speedup vs baseline: 1.0019x; 1.0019x over previous
#include <cuda_runtime.h>
#include <math.h>
#include <stdint.h>

#define BATCH 128

// ----------------- scratch buffers -----------------
__device__ float d_c1[BATCH*96*55*55];
__device__ float d_l1[BATCH*96*27*27];
__device__ float d_c2[BATCH*256*27*27];
__device__ float d_l2[BATCH*256*13*13];
__device__ float d_c3[BATCH*384*13*13];
__device__ float d_c4[BATCH*384*13*13];
__device__ float d_c5[BATCH*256*13*13];
__device__ float d_feat[BATCH*9216];
__device__ float d_h1[BATCH*4096];
__device__ float d_h2[BATCH*4096];
__device__ float d_out0[BATCH*100];
__device__ float d_g2[BATCH*4096];
__device__ float d_mask[BATCH*36];
__device__ float d_h1b[BATCH*4096];
__device__ float d_h2b[BATCH*4096];
__device__ float d_outb[BATCH*100];
__device__ float d_clsb[BATCH];
__device__ float d_w6r[4096*36];
__device__ float d_part[8*BATCH*4096];

// ----------------- f32x2 helpers -----------------
__device__ __forceinline__ unsigned long long pack2(float a, float b) {
    unsigned long long r;
    asm("mov.b64 %0, {%1, %2};" : "=l"(r) : "r"(__float_as_uint(a)), "r"(__float_as_uint(b)));
    return r;
}
__device__ __forceinline__ void fma2(unsigned long long& d, unsigned long long a, unsigned long long b) {
    asm("fma.rn.f32x2 %0, %1, %2, %0;" : "+l"(d) : "l"(a), "l"(b));
}
__device__ __forceinline__ float2 unpack2(unsigned long long v) {
    unsigned lo, hi;
    asm("mov.b64 {%0, %1}, %2;" : "=r"(lo), "=r"(hi) : "l"(v));
    float2 f; f.x = __uint_as_float(lo); f.y = __uint_as_float(hi); return f;
}

// ----------------- implicit-GEMM conv, f32x2, double-buffered (frozen) -----------------
template<int CING, int HH, int WW, int COUTG, int COUTT, int KH, int KW,
         int STR, int PAD, int OH, int OW, int GROUPS, int MT>
__global__ __launch_bounds__(256, 2)
void conv_f2(const float* __restrict__ x, const float* __restrict__ w,
             const float* __restrict__ bias, float* __restrict__ out, float scale)
{
    constexpr int K    = CING*KH*KW;
    constexpr int CINT = CING*GROUPS;
    constexpr int OHW  = OH*OW;
    constexpr int MI   = MT/16;
    constexpr int AS   = MT + 4;
    constexpr int NCH  = (K + 15)/16;

    const int g    = blockIdx.z;
    const int pix0 = blockIdx.x * 128;
    const int m0   = blockIdx.y * MT;

    __shared__ __align__(16) float As[2][16][AS];
    __shared__ __align__(16) float Bs[2][16][132];

    const int t  = threadIdx.x;
    const int tx = t & 15, ty = t >> 4;
    const int lk = t & 15, lr = t >> 4;

    int ihb[8], iwb[8], xb[8];
    #pragma unroll
    for (int p = 0; p < 8; ++p) {
        int pix = pix0 + lr + p*16;
        int n   = pix / OHW; int rem = pix - n*OHW;
        int oh  = rem / OW;  int ow  = rem - oh*OW;
        ihb[p] = oh*STR - PAD; iwb[p] = ow*STR - PAD;
        xb[p]  = (n*CINT + g*CING)*HH*WW;
    }

    const float* wbase = w + (size_t)(g*COUTG + m0)*K;

    float ra[MI], rb[8];

    auto loadA = [&](int k0) {
        int kg = k0 + lk; bool kv = kg < K;
        #pragma unroll
        for (int p = 0; p < MI; ++p)
            ra[p] = kv ? wbase[(lr + p*16)*K + kg] : 0.f;
    };
    auto loadB = [&](int k0) {
        int kg = k0 + lk; bool kv = kg < K;
        int kc = kv ? kg : 0;
        int ic = kc / (KH*KW);
        int r2 = kc - ic*(KH*KW);
        int kh = r2 / KW, kw = r2 - kh*KW;
        #pragma unroll
        for (int p = 0; p < 8; ++p) {
            int ih = ihb[p] + kh, iw = iwb[p] + kw;
            float v = 0.f;
            if (kv && (unsigned)ih < (unsigned)HH && (unsigned)iw < (unsigned)WW)
                v = x[xb[p] + ic*HH*WW + ih*WW + iw] * scale;
            rb[p] = v;
        }
    };
    auto stTile = [&](int buf) {
        #pragma unroll
        for (int p = 0; p < MI; ++p) As[buf][lk][lr + p*16] = ra[p];
        #pragma unroll
        for (int p = 0; p < 8;  ++p) Bs[buf][lk][lr + p*16] = rb[p];
    };

    unsigned long long acc[MI][4];
    #pragma unroll
    for (int i = 0; i < MI; ++i)
        #pragma unroll
        for (int j = 0; j < 4; ++j) acc[i][j] = 0ull;

    loadA(0); loadB(0); stTile(0);
    __syncthreads();

    for (int c = 0; c < NCH; ++c) {
        int buf = c & 1;
        if (c + 1 < NCH) { loadA((c+1)*16); loadB((c+1)*16); }
        #pragma unroll
        for (int kk = 0; kk < 16; ++kk) {
            unsigned long long b2[4];
            #pragma unroll
            for (int j = 0; j < 4; ++j)
                b2[j] = *(const unsigned long long*)&Bs[buf][kk][tx*2 + j*32];
            #pragma unroll
            for (int i = 0; i < MI; ++i) {
                float av = As[buf][kk][ty + i*16];
                unsigned long long a2 = pack2(av, av);
                #pragma unroll
                for (int j = 0; j < 4; ++j) fma2(acc[i][j], a2, b2[j]);
            }
        }
        if (c + 1 < NCH) stTile(buf ^ 1);
        __syncthreads();
    }

    #pragma unroll
    for (int i = 0; i < MI; ++i) {
        int m = m0 + ty + i*16;
        float bv = bias[g*COUTG + m];
        #pragma unroll
        for (int j = 0; j < 4; ++j) {
            float2 v = unpack2(acc[i][j]);
            int pix = pix0 + tx*2 + j*32;
            int n0_ = pix / OHW;       int r0_ = pix - n0_*OHW;
            int n1_ = (pix+1) / OHW;   int r1_ = (pix+1) - n1_*OHW;
            out[((size_t)(n0_*COUTT + g*COUTG + m))*OHW + r0_] = fmaxf(v.x + bv, 0.f);
            out[((size_t)(n1_*COUTT + g*COUTG + m))*OHW + r1_] = fmaxf(v.y + bv, 0.f);
        }
    }
}

// ----------------- split-K GEMM, f32x2, 64x64 tiles (frozen) -----------------
template<int TRANSB>
__global__ __launch_bounds__(256, 2)
void gemm_f2(const float* __restrict__ A, const float* __restrict__ B,
             float* __restrict__ part, int M, int N, int K, int Kc)
{
    __shared__ __align__(16) float As[2][16][68];
    __shared__ __align__(16) float Bs[2][16][68];
    const int m0 = blockIdx.y*64, n0 = blockIdx.x*64;
    const int z  = blockIdx.z;
    const int kb = z*Kc;
    const int ke = min(K, kb + Kc);
    const int t = threadIdx.x, tx = t & 15, ty = t >> 4;
    const int lk = t & 15, lr = t >> 4;
    const int lr2 = t & 63, lk2 = t >> 6;

    float ra[4], rbv[4];
    auto loadA = [&](int k0) {
        int kg = k0 + lk; bool kv = kg < ke;
        #pragma unroll
        for (int p = 0; p < 4; ++p)
            ra[p] = kv ? A[(size_t)(m0 + lr + p*16)*K + kg] : 0.f;
    };
    auto loadB = [&](int k0) {
        if (TRANSB) {
            int kg = k0 + lk; bool kv = kg < ke;
            #pragma unroll
            for (int p = 0; p < 4; ++p)
                rbv[p] = kv ? B[(size_t)(n0 + lr + p*16)*K + kg] : 0.f;
        } else {
            #pragma unroll
            for (int p = 0; p < 4; ++p) {
                int kg = k0 + lk2 + p*4;
                rbv[p] = (kg < ke) ? B[(size_t)kg*N + n0 + lr2] : 0.f;
            }
        }
    };
    auto stT = [&](int buf) {
        #pragma unroll
        for (int p = 0; p < 4; ++p) As[buf][lk][lr + p*16] = ra[p];
        if (TRANSB) {
            #pragma unroll
            for (int p = 0; p < 4; ++p) Bs[buf][lk][lr + p*16] = rbv[p];
        } else {
            #pragma unroll
            for (int p = 0; p < 4; ++p) Bs[buf][lk2 + p*4][lr2] = rbv[p];
        }
    };

    unsigned long long acc[4][2];
    #pragma unroll
    for (int i = 0; i < 4; ++i) { acc[i][0] = 0ull; acc[i][1] = 0ull; }

    const int nch = (ke - kb + 15)/16;
    loadA(kb); loadB(kb); stT(0);
    __syncthreads();

    for (int c = 0; c < nch; ++c) {
        int buf = c & 1;
        if (c + 1 < nch) { loadA(kb + (c+1)*16); loadB(kb + (c+1)*16); }
        #pragma unroll
        for (int kk = 0; kk < 16; ++kk) {
            unsigned long long b2[2];
            #pragma unroll
            for (int j = 0; j < 2; ++j)
                b2[j] = *(const unsigned long long*)&Bs[buf][kk][tx*2 + j*32];
            #pragma unroll
            for (int i = 0; i < 4; ++i) {
                float av = As[buf][kk][ty + i*16];
                unsigned long long a2 = pack2(av, av);
                #pragma unroll
                for (int j = 0; j < 2; ++j) fma2(acc[i][j], a2, b2[j]);
            }
        }
        if (c + 1 < nch) stT(buf ^ 1);
        __syncthreads();
    }

    #pragma unroll
    for (int i = 0; i < 4; ++i) {
        int m = m0 + ty + i*16;
        #pragma unroll
        for (int j = 0; j < 2; ++j) {
            float2 v = unpack2(acc[i][j]);
            int n = n0 + tx*2 + j*32;
            *(float2*)&part[((size_t)z*M + m)*N + n] = v;
        }
    }
}

// ----------------- masked-A variant (head#2 first GEMM) -----------------
__global__ __launch_bounds__(256, 2)
void gemm_f2m(const float* __restrict__ A, const float* __restrict__ B,
              const float* __restrict__ mask,
              float* __restrict__ part, int M, int N, int K, int Kc)
{
    __shared__ __align__(16) float As[2][16][68];
    __shared__ __align__(16) float Bs[2][16][68];
    const int m0 = blockIdx.y*64, n0 = blockIdx.x*64;
    const int z  = blockIdx.z;
    const int kb = z*Kc;
    const int ke = min(K, kb + Kc);
    const int t = threadIdx.x, tx = t & 15, ty = t >> 4;
    const int lk = t & 15, lr = t >> 4;

    float ra[4], rbv[4];
    auto loadA = [&](int k0) {
        int kg = k0 + lk; bool kv = kg < ke;
        int s = kg % 36;
        #pragma unroll
        for (int p = 0; p < 4; ++p) {
            int row = m0 + lr + p*16;
            float mv = mask[row*36 + s];
            ra[p] = kv ? A[(size_t)row*K + kg] * mv : 0.f;
        }
    };
    auto loadB = [&](int k0) {
        int kg = k0 + lk; bool kv = kg < ke;
        #pragma unroll
        for (int p = 0; p < 4; ++p)
            rbv[p] = kv ? B[(size_t)(n0 + lr + p*16)*K + kg] : 0.f;
    };
    auto stT = [&](int buf) {
        #pragma unroll
        for (int p = 0; p < 4; ++p) As[buf][lk][lr + p*16] = ra[p];
        #pragma unroll
        for (int p = 0; p < 4; ++p) Bs[buf][lk][lr + p*16] = rbv[p];
    };

    unsigned long long acc[4][2];
    #pragma unroll
    for (int i = 0; i < 4; ++i) { acc[i][0] = 0ull; acc[i][1] = 0ull; }

    const int nch = (ke - kb + 15)/16;
    loadA(kb); loadB(kb); stT(0);
    __syncthreads();

    for (int c = 0; c < nch; ++c) {
        int buf = c & 1;
        if (c + 1 < nch) { loadA(kb + (c+1)*16); loadB(kb + (c+1)*16); }
        #pragma unroll
        for (int kk = 0; kk < 16; ++kk) {
            unsigned long long b2[2];
            #pragma unroll
            for (int j = 0; j < 2; ++j)
                b2[j] = *(const unsigned long long*)&Bs[buf][kk][tx*2 + j*32];
            #pragma unroll
            for (int i = 0; i < 4; ++i) {
                float av = As[buf][kk][ty + i*16];
                unsigned long long a2 = pack2(av, av);
                #pragma unroll
                for (int j = 0; j < 2; ++j) fma2(acc[i][j], a2, b2[j]);
            }
        }
        if (c + 1 < nch) stT(buf ^ 1);
        __syncthreads();
    }

    #pragma unroll
    for (int i = 0; i < 4; ++i) {
        int m = m0 + ty + i*16;
        #pragma unroll
        for (int j = 0; j < 2; ++j) {
            float2 v = unpack2(acc[i][j]);
            int n = n0 + tx*2 + j*32;
            *(float2*)&part[((size_t)z*M + m)*N + n] = v;
        }
    }
}

// ----------------- split-K reduce + bias/relu epilogue (N=4096) -----------------
__global__ void reduce_k(const float* __restrict__ part, const float* __restrict__ bias,
                         const float* __restrict__ maskref, float* __restrict__ C,
                         int MN, int S, int doRelu)
{
    int i = blockIdx.x*256 + threadIdx.x;
    if (i >= MN) return;
    float s = 0.f;
    for (int z = 0; z < S; ++z) s += part[(size_t)z*MN + i];
    if (bias) s += bias[i & 4095];
    if (doRelu) s = fmaxf(s, 0.f);
    if (maskref) s = (maskref[i] > 0.f) ? s : 0.f;
    C[i] = s;
}

// ----------------- split-K reduce producing h2 AND g2 -----------------
__global__ void reduce_g2_k(const float* __restrict__ part, const float* __restrict__ bias,
                            const float* __restrict__ wc, const int* __restrict__ gt,
                            float* __restrict__ h2, float* __restrict__ g2, int S)
{
    int i = blockIdx.x*256 + threadIdx.x;
    if (i >= BATCH*4096) return;
    int n = i >> 12, j = i & 4095;
    float s = 0.f;
    for (int z = 0; z < S; ++z) s += part[(size_t)z*BATCH*4096 + i];
    s += bias[j];
    s = fmaxf(s, 0.f);
    h2[i] = s;
    g2[i] = (s > 0.f) ? wc[(size_t)gt[n]*4096 + j] : 0.f;
}

// ----------------- fused gradient tail: reduce(g1) + spatial-mean GEMM + RSC mask -----------------
__global__ void gradtail_k(const float* __restrict__ part, const float* __restrict__ h1,
                           const float* __restrict__ w6r, const float* __restrict__ u,
                           const int* __restrict__ flag, float* __restrict__ mask)
{
    __shared__ float gs[4096];
    __shared__ float smrow[36];
    const int n = blockIdx.x, t = threadIdx.x;
    const int warp = t >> 5, lane = t & 31;

    for (int j = t; j < 4096; j += 256) {
        size_t i = (size_t)n*4096 + j;
        float s = 0.f;
        #pragma unroll
        for (int z = 0; z < 8; ++z) s += part[(size_t)z*BATCH*4096 + i];
        gs[j] = (h1[i] > 0.f) ? s : 0.f;
    }
    __syncthreads();

    for (int s = warp; s < 36; s += 8) {
        float acc = 0.f;
        for (int k = lane; k < 4096; k += 32) acc += gs[k] * w6r[k*36 + s];
        #pragma unroll
        for (int o = 16; o; o >>= 1) acc += __shfl_xor_sync(0xffffffffu, acc, o);
        if (lane == 0) smrow[s] = acc;
    }
    __syncthreads();

    if (t == 0) {
        if (*flag == 0) {
            for (int s = 0; s < 36; ++s) mask[n*36 + s] = 1.f;
            return;
        }
        float v[36], tmp[36], sc[36], mk[36];
        for (int s = 0; s < 36; ++s) { v[s] = smrow[s]; tmp[s] = v[s]; mk[s] = 1.f; }
        float th = 0.f;
        for (int it = 0; it < 13; ++it) {
            int bi = 0; float bv = tmp[0];
            for (int s = 1; s < 36; ++s) if (tmp[s] > bv) { bv = tmp[s]; bi = s; }
            th = bv; tmp[bi] = -3.4e38f;
        }
        for (int s = 0; s < 36; ++s) sc[s] = (v[s] >= th) ? u[n*36 + s] : -1.f;
        for (int it = 0; it < 12; ++it) {
            int bi = 0; float bv = sc[0];
            for (int s = 1; s < 36; ++s) if (sc[s] > bv) { bv = sc[s]; bi = s; }
            mk[bi] = 0.f; sc[bi] = -2.f;
        }
        for (int s = 0; s < 36; ++s) mask[n*36 + s] = mk[s];
    }
}

// ----------------- fused maxpool(3,2) + LRN(n=5) -----------------
template<int C, int HI, int HO>
__global__ void poollrn_kernel(const float* __restrict__ in, float* __restrict__ out)
{
    __shared__ float pl[C*HO];
    int b = blockIdx.x;
    int n = b / HO, oy = b % HO;
    for (int idx = threadIdx.x; idx < C*HO; idx += 256) {
        int c = idx / HO, ox = idx - c*HO;
        const float* p = in + ((size_t)(n*C + c)*HI + oy*2)*HI + ox*2;
        float m = -3.4e38f;
        #pragma unroll
        for (int a = 0; a < 3; ++a)
            #pragma unroll
            for (int bq = 0; bq < 3; ++bq)
                m = fmaxf(m, p[a*HI + bq]);
        pl[idx] = m;
    }
    __syncthreads();
    for (int idx = threadIdx.x; idx < C*HO; idx += 256) {
        int c = idx / HO, ox = idx - c*HO;
        float sum = 0.f;
        #pragma unroll
        for (int d = -2; d <= 2; ++d) {
            int cc = c + d;
            if (cc >= 0 && cc < C) {
                float v = pl[cc*HO + ox];
                sum = fmaf(v, v, sum);
            }
        }
        float r = rsqrtf(fmaf(2e-5f, sum, 1.0f));
        out[((size_t)(n*C + c)*HO + oy)*HO + ox] = pl[idx] * r * sqrtf(r);
    }
}

// ----------------- maxpool 3x3 stride 2 (final 13->6) -----------------
template<int C, int HI, int HO>
__global__ void pool_kernel(const float* __restrict__ in, float* __restrict__ out)
{
    constexpr int TOT = BATCH*C*HO*HO;
    int idx = blockIdx.x*256 + threadIdx.x;
    if (idx >= TOT) return;
    int ox = idx % HO;
    int tq = idx / HO;
    int oy = tq % HO;
    int nc = tq / HO;
    const float* p = in + ((size_t)nc*HI + oy*2)*HI + ox*2;
    float m = -3.4e38f;
    #pragma unroll
    for (int a = 0; a < 3; ++a)
        #pragma unroll
        for (int b = 0; b < 3; ++b)
            m = fmaxf(m, p[a*HI + b]);
    out[idx] = m;
}

// ----------------- fold w6 over channels -----------------
__global__ void w6fold_k(const float* __restrict__ w6, float* __restrict__ w6r)
{
    int i = blockIdx.x*256 + threadIdx.x;
    if (i >= 4096*36) return;
    int j = i / 36, s = i - j*36;
    const float* p = w6 + (size_t)j*9216 + s;
    float acc = 0.f;
    for (int c = 0; c < 256; ++c) acc += p[c*36];
    w6r[i] = acc * (1.f/256.f);
}

// ----------------- classifier dot -----------------
__global__ void cls_kernel(const float* __restrict__ h, const float* __restrict__ wc,
                           const float* __restrict__ bc, float* __restrict__ out)
{
    int n = blockIdx.x;
    int warp = threadIdx.x >> 5, lane = threadIdx.x & 31;
    int c = blockIdx.y*8 + warp;
    if (c >= 100) return;
    const float4* hp = (const float4*)(h + n*4096);
    const float4* wp = (const float4*)(wc + c*4096);
    float s = 0.f;
    for (int k = lane; k < 1024; k += 32) {
        float4 a = hp[k], b = wp[k];
        s += a.x*b.x + a.y*b.y + a.z*b.z + a.w*b.w;
    }
    #pragma unroll
    for (int o = 16; o; o >>= 1) s += __shfl_xor_sync(0xffffffffu, s, o);
    if (lane == 0) out[n*100 + c] = s + bc[c];
}

// ----------------- softmax probability at gt (head#1, side stream) -----------------
__global__ void softgt_kernel(const float* __restrict__ logits, const int* __restrict__ gt,
                              float* __restrict__ cls)
{
    int n = blockIdx.x;
    int lane = threadIdx.x;
    float m = -3.4e38f;
    for (int c = lane; c < 100; c += 32) m = fmaxf(m, logits[n*100 + c]);
    #pragma unroll
    for (int o = 16; o; o >>= 1) m = fmaxf(m, __shfl_xor_sync(0xffffffffu, m, o));
    float s = 0.f;
    for (int c = lane; c < 100; c += 32) s += expf(logits[n*100 + c] - m);
    #pragma unroll
    for (int o = 16; o; o >>= 1) s += __shfl_xor_sync(0xffffffffu, s, o);
    if (lane == 0) cls[n] = expf(logits[n*100 + gt[n]] - m) / s;
}

// ----------------- fused head#2 softmax@gt + keep decision + final row select -----------------
// 1 block x 1024 threads; warp w handles rows {w, w+32, ...} with softgt's exact
// lane-stride + shfl-tree arithmetic (bit-identical clsa), then verbatim keepsel.
__global__ void finsel_k(const float* __restrict__ outb, const int* __restrict__ gt,
                         const float* __restrict__ clsb, const float* __restrict__ out0,
                         float* __restrict__ out)
{
    __shared__ float cv[BATCH];
    __shared__ float thf;
    const int t = threadIdx.x, warp = t >> 5, lane = t & 31;

    for (int n = warp; n < BATCH; n += 32) {
        float m = -3.4e38f;
        for (int c = lane; c < 100; c += 32) m = fmaxf(m, outb[n*100 + c]);
        #pragma unroll
        for (int o = 16; o; o >>= 1) m = fmaxf(m, __shfl_xor_sync(0xffffffffu, m, o));
        float s = 0.f;
        for (int c = lane; c < 100; c += 32) s += expf(outb[n*100 + c] - m);
        #pragma unroll
        for (int o = 16; o; o >>= 1) s += __shfl_xor_sync(0xffffffffu, s, o);
        if (lane == 0) {
            float clsa = expf(outb[n*100 + gt[n]] - m) / s;
            cv[n] = fmaxf(clsb[n] - clsa - 1e-4f, 0.f);
        }
    }
    __syncthreads();
    if (t == 0) {
        float tmp[BATCH];
        for (int i = 0; i < BATCH; ++i) tmp[i] = cv[i];
        float bv = 0.f;
        for (int it = 0; it < 44; ++it) {
            int bi = 0; bv = tmp[0];
            for (int i = 1; i < BATCH; ++i) if (tmp[i] > bv) { bv = tmp[i]; bi = i; }
            tmp[bi] = -3.4e38f;
        }
        thf = bv;
    }
    __syncthreads();
    for (int i = t; i < BATCH*100; i += 1024) {
        int n = i / 100;
        bool keep = !(cv[n] > thf);
        out[i] = keep ? out0[i] : outb[i];
    }
}

// ----------------- launch -----------------
static float* sym(const void* symbol)
{
    void* p = nullptr;
    cudaGetSymbolAddress(&p, symbol);
    return (float*)p;
}

extern "C" void kernel_launch(void* const* d_in, const int* in_sizes, int n_in,
                              void* d_out, int out_size)
{
    const float* x    = (const float*)d_in[0];
    const int*   gt   = (const int*)  d_in[1];
    const float* u    = (const float*)d_in[2];
    const int*   flag = (const int*)  d_in[3];
    const float* w1 = (const float*)d_in[4];  const float* b1 = (const float*)d_in[5];
    const float* w2 = (const float*)d_in[6];  const float* b2 = (const float*)d_in[7];
    const float* w3 = (const float*)d_in[8];  const float* b3 = (const float*)d_in[9];
    const float* w4 = (const float*)d_in[10]; const float* b4 = (const float*)d_in[11];
    const float* w5 = (const float*)d_in[12]; const float* b5 = (const float*)d_in[13];
    const float* w6 = (const float*)d_in[14]; const float* b6 = (const float*)d_in[15];
    const float* w7 = (const float*)d_in[16]; const float* b7 = (const float*)d_in[17];
    const float* wc = (const float*)d_in[18]; const float* bc = (const float*)d_in[19];
    float* out = (float*)d_out;

    float* c1   = sym(d_c1);   float* l1   = sym(d_l1);
    float* c2   = sym(d_c2);   float* l2   = sym(d_l2);
    float* c3   = sym(d_c3);   float* c4   = sym(d_c4);   float* c5   = sym(d_c5);
    float* feat = sym(d_feat);
    float* h1   = sym(d_h1);   float* h2   = sym(d_h2);   float* out0 = sym(d_out0);
    float* g2   = sym(d_g2);
    float* mask = sym(d_mask);
    float* h1b  = sym(d_h1b);  float* h2b  = sym(d_h2b);
    float* outb = sym(d_outb); float* clsb = sym(d_clsb);
    float* w6r  = sym(d_w6r);  float* part = sym(d_part);

    const int MN = BATCH*4096;

    // side stream + fork/join events (handles cached; identical work every call)
    static cudaStream_t side = nullptr;
    static cudaEvent_t evF1 = nullptr, evJ1 = nullptr, evF2 = nullptr, evJ2 = nullptr;
    if (!side) {
        cudaStreamCreateWithFlags(&side, cudaStreamNonBlocking);
        cudaEventCreateWithFlags(&evF1, cudaEventDisableTiming);
        cudaEventCreateWithFlags(&evJ1, cudaEventDisableTiming);
        cudaEventCreateWithFlags(&evF2, cudaEventDisableTiming);
        cudaEventCreateWithFlags(&evJ2, cudaEventDisableTiming);
        // maximize L1 cache for conv scattered gathers (hint; smem need is 68KB/SM)
        cudaFuncSetAttribute(conv_f2<3,227,227,96,96,11,11,4,0,55,55,1,96>,  cudaFuncAttributePreferredSharedMemoryCarveout, 32);
        cudaFuncSetAttribute(conv_f2<48,27,27,128,256,5,5,1,2,27,27,2,128>,  cudaFuncAttributePreferredSharedMemoryCarveout, 32);
        cudaFuncSetAttribute(conv_f2<256,13,13,384,384,3,3,1,1,13,13,1,128>, cudaFuncAttributePreferredSharedMemoryCarveout, 32);
        cudaFuncSetAttribute(conv_f2<192,13,13,192,384,3,3,1,1,13,13,2,96>,  cudaFuncAttributePreferredSharedMemoryCarveout, 32);
        cudaFuncSetAttribute(conv_f2<192,13,13,128,256,3,3,1,1,13,13,2,128>, cudaFuncAttributePreferredSharedMemoryCarveout, 32);
    }

    // ---- fork: w6fold on side stream, overlapping the conv stack ----
    cudaEventRecord(evF1, 0);
    cudaStreamWaitEvent(side, evF1, 0);
    w6fold_k<<<(4096*36 + 255)/256, 256, 0, side>>>(w6, w6r);
    cudaEventRecord(evJ1, side);

    // ---- feature extractor (frozen) ----
    conv_f2<3,227,227,96,96,11,11,4,0,55,55,1,96><<<dim3(3025,1,1),256>>>(x, w1, b1, c1, 57.6f);
    poollrn_kernel<96,55,27><<<BATCH*27,256>>>(c1, l1);
    conv_f2<48,27,27,128,256,5,5,1,2,27,27,2,128><<<dim3(729,1,2),256>>>(l1, w2, b2, c2, 1.f);
    poollrn_kernel<256,27,13><<<BATCH*13,256>>>(c2, l2);
    conv_f2<256,13,13,384,384,3,3,1,1,13,13,1,128><<<dim3(169,3,1),256>>>(l2, w3, b3, c3, 1.f);
    conv_f2<192,13,13,192,384,3,3,1,1,13,13,2,96><<<dim3(169,2,2),256>>>(c3, w4, b4, c4, 1.f);
    conv_f2<192,13,13,128,256,3,3,1,1,13,13,2,128><<<dim3(169,1,2),256>>>(c4, w5, b5, c5, 1.f);
    pool_kernel<256,13,6><<<4608,256>>>(c5, feat);

    // ---- head #1 (unmasked) : split-K 8 (frozen) ----
    gemm_f2<1><<<dim3(64,2,8),256>>>(feat, w6, part, 128, 4096, 9216, 1152);
    reduce_k<<<2048,256>>>(part, b6, nullptr, h1, MN, 8, 1);
    gemm_f2<1><<<dim3(64,2,8),256>>>(h1, w7, part, 128, 4096, 4096, 512);
    reduce_g2_k<<<2048,256>>>(part, b7, wc, gt, h2, g2, 8);   // produces h2 + g2

    // ---- fork: head#1 cls/softgt on side stream, overlapping the gradient chain ----
    cudaEventRecord(evF2, 0);
    cudaStreamWaitEvent(side, evF2, 0);
    cls_kernel<<<dim3(128,13), 256, 0, side>>>(h2, wc, bc, out0);
    softgt_kernel<<<128, 32, 0, side>>>(out0, gt, clsb);
    cudaEventRecord(evJ2, side);

    // ---- gradient chain: g1-GEMM then fused reduce+smgemm+mask tail ----
    gemm_f2<0><<<dim3(64,2,8),256>>>(g2, w7, part, 128, 4096, 4096, 512);
    cudaStreamWaitEvent(0, evJ1, 0);           // w6r ready
    gradtail_k<<<128,256>>>(part, h1, w6r, u, flag, mask);

    // ---- head #2 (masked) : mask folded into first GEMM's A-load ----
    gemm_f2m<<<dim3(64,2,8),256>>>(feat, w6, mask, part, 128, 4096, 9216, 1152);
    reduce_k<<<2048,256>>>(part, b6, nullptr, h1b, MN, 8, 1);
    gemm_f2<1><<<dim3(64,2,8),256>>>(h1b, w7, part, 128, 4096, 4096, 512);
    reduce_k<<<2048,256>>>(part, b7, nullptr, h2b, MN, 8, 1);
    cls_kernel<<<dim3(128,13),256>>>(h2b, wc, bc, outb);

    // ---- join head#1 cls chain, then fused softmax@gt + keep + select ----
    cudaStreamWaitEvent(0, evJ2, 0);
    finsel_k<<<1,1024>>>(outb, gt, clsb, out0, out);

    (void)in_sizes; (void)n_in; (void)out_size;
}